// round 12
// baseline (speedup 1.0000x reference)
#include <cuda_runtime.h>
#include <cuda_fp16.h>
#include <cstdint>

// Problem constants (from reference)
#define BATCH 16384
#define EMBED 1024
#define SEQ   7
#define E2    (EMBED / 2)       // 512 half2 (float2) lanes per full row
#define EQ2   128               // half2 lanes per quarter (256 channels)
#define NQ    4                 // channel quarters (grid.y)
#define ROWS_PER_CTA 8
#define ROWS_PER_IT  2          // 256 threads / 128 lanes
#define THREADS 256

// reinterpret helpers
__device__ __forceinline__ __half2 u2h2(unsigned r) {
    __half2 h; *reinterpret_cast<unsigned*>(&h) = r; return h;
}
__device__ __forceinline__ unsigned h22u(__half2 h) {
    return *reinterpret_cast<unsigned*>(&h);
}
// packed f16x2 tanh: one MUFU op for two channels
__device__ __forceinline__ __half2 tanh2h(__half2 x) {
    unsigned r = h22u(x);
    asm("tanh.approx.f16x2 %0, %0;" : "+r"(r));
    return u2h2(r);
}
// scaled float pair -> half2
__device__ __forceinline__ __half2 mk2(float2 v, float s) {
    return __floats2half2_rn(v.x * s, v.y * s);
}
__device__ __forceinline__ __half2 mk2b(float2 p, float2 q, float s) {
    return __floats2half2_rn((p.x + q.x) * s, (p.y + q.y) * s);
}
__device__ __forceinline__ __half2 mk3b(float2 p, float2 q, float2 r, float s) {
    return __floats2half2_rn((p.x + q.x + r.x) * s, (p.y + q.y + r.y) * s);
}

// Each thread owns ONE half2 stream (2 channels). 128 lanes x 2 rows per CTA
// iteration; blockIdx.y = channel quarter (x-fastest CTA order keeps each
// quarter's 32.7MB gather footprint L2-resident).
__global__ void __launch_bounds__(THREADS, 6)
conv_cascade_q_kernel(const int* __restrict__ X,
                      const float2* __restrict__ emb,   // (VOCAB, E2)
                      const float2* __restrict__ c1,    // (2, E2)
                      const float2* __restrict__ c2,    // (2, E2)
                      const float2* __restrict__ c3,    // (3, E2)
                      const float2* __restrict__ c4,    // (3, E2)
                      float2* __restrict__ out)         // (BATCH, E2)
{
    const int lane = threadIdx.x & (EQ2 - 1);           // 0..127 half2 lane
    const int rsub = threadIdx.x >> 7;                  // 0..1 row within iter
    const int e2   = blockIdx.y * EQ2 + lane;           // global half2 lane
    const int b0   = blockIdx.x * ROWS_PER_CTA;

    __shared__ int idx[ROWS_PER_CTA][SEQ];
    if (threadIdx.x < ROWS_PER_CTA * SEQ) {
        int r = threadIdx.x / SEQ;
        int t = threadIdx.x % SEQ;
        idx[r][t] = X[(b0 + r) * SEQ + t];
    }

    // Tanh-domain scaled weights in registers (13 half2 = 13 regs).
    // Stage1: w/2 no bias; stages 2-4: w/4 with bias = sum(w)/4.
    float2 a0 = c1[0 * E2 + e2], a1 = c1[1 * E2 + e2];
    float2 d0 = c2[0 * E2 + e2], d1 = c2[1 * E2 + e2];
    float2 e0 = c3[0 * E2 + e2], e1 = c3[1 * E2 + e2], e2v = c3[2 * E2 + e2];
    float2 f0 = c4[0 * E2 + e2], f1 = c4[1 * E2 + e2], f2 = c4[2 * E2 + e2];

    const __half2 W10 = mk2(a0, 0.5f),  W11 = mk2(a1, 0.5f);
    const __half2 V0  = mk2(d0, 0.25f), V1  = mk2(d1, 0.25f);
    const __half2 B2  = mk2b(d0, d1, 0.25f);
    const __half2 U0  = mk2(e0, 0.25f), U1  = mk2(e1, 0.25f), U2 = mk2(e2v, 0.25f);
    const __half2 B3  = mk3b(e0, e1, e2v, 0.25f);
    const __half2 T0  = mk2(f0, 0.25f), T1  = mk2(f1, 0.25f), T2 = mk2(f2, 0.25f);
    const __half2 B4  = mk3b(f0, f1, f2, 0.25f);
    const __half2 HALF = __float2half2_rn(0.5f);

    __syncthreads();

#pragma unroll 1
    for (int it = 0; it < ROWS_PER_CTA / ROWS_PER_IT; ++it) {
        const int r = it * ROWS_PER_IT + rsub;

        // Gather 7 embedding float2s -> half2 (edge conversion only).
        __half2 h[SEQ];
#pragma unroll
        for (int t = 0; t < SEQ; ++t) {
            long row = (long)idx[r][t];
            float2 v = __ldg(&emb[row * E2 + e2]);
            h[t] = __floats2half2_rn(v.x, v.y);
        }

        // Stage 1 (size-2, raw input, scale 1/2, no bias)
        __half2 p[6];
#pragma unroll
        for (int t = 0; t < 6; ++t)
            p[t] = tanh2h(__hfma2(W10, h[t], __hmul2(W11, h[t + 1])));

        // Stage 2 (size-2, tanh-domain, scale 1/4 + bias)
        __half2 q[5];
#pragma unroll
        for (int t = 0; t < 5; ++t)
            q[t] = tanh2h(__hfma2(V0, p[t], __hfma2(V1, p[t + 1], B2)));

        // Stage 3 (size-3)
        __half2 s[3];
#pragma unroll
        for (int t = 0; t < 3; ++t)
            s[t] = tanh2h(__hfma2(U0, q[t],
                       __hfma2(U1, q[t + 1], __hfma2(U2, q[t + 2], B3))));

        // Stage 4 (size-3) + final affine back to sigma
        __half2 res = tanh2h(__hfma2(T0, s[0],
                        __hfma2(T1, s[1], __hfma2(T2, s[2], B4))));
        res = __hfma2(res, HALF, HALF);

        float2 f = __half22float2(res);
        __stcs(&out[(long)(b0 + r) * E2 + e2], f);
    }
}

extern "C" void kernel_launch(void* const* d_in, const int* in_sizes, int n_in,
                              void* d_out, int out_size)
{
    const int*    X    = (const int*)d_in[0];
    const float2* emb  = (const float2*)d_in[1];
    const float2* c1   = (const float2*)d_in[2];
    const float2* c2   = (const float2*)d_in[3];
    const float2* c3   = (const float2*)d_in[4];
    const float2* c4   = (const float2*)d_in[5];
    float2*       out  = (float2*)d_out;

    dim3 grid(BATCH / ROWS_PER_CTA, NQ);   // (2048, 4) — x fastest => quarter order
    dim3 block(THREADS);
    conv_cascade_q_kernel<<<grid, block>>>(X, emb, c1, c2, c3, c4, out);
}